// round 11
// baseline (speedup 1.0000x reference)
#include <cuda_runtime.h>
#include <cstdint>

#define NNODES 50000
#define EDGES  800000
#define DD 128
#define LN_EPS 1e-5f

// ---- scratch (device globals; no allocation allowed) ----
__device__ float g_h1[(size_t)NNODES * DD];    // layer-1 output
__device__ float g_iso[NNODES];
__device__ float g_isi[NNODES];
__device__ int   g_din[NNODES];
__device__ int   g_dout[NNODES];
__device__ int   g_cnt[NNODES];
__device__ int   g_off[NNODES + 1];
__device__ int   g_csr_src[EDGES];

// ---- CSR build ----
__global__ void zero_counts(int n) {
    int i = blockIdx.x * blockDim.x + threadIdx.x;
    if (i < n) { g_din[i] = 0; g_dout[i] = 0; g_cnt[i] = 0; }
}

__global__ void deg_count(const int* __restrict__ src,
                          const int* __restrict__ dst, int e) {
    int i = blockIdx.x * blockDim.x + threadIdx.x;
    if (i < e) {
        atomicAdd(&g_dout[src[i]], 1);
        atomicAdd(&g_din[dst[i]], 1);
    }
}

// ---- single-block scan over g_din + finalize offsets/iso/isi ----
// 1024 threads, each handles a contiguous chunk serially.
__global__ void scan_finalize(int n, int e) {
    __shared__ int wsums[32];
    int t = threadIdx.x;
    int lane = t & 31, w = t >> 5;
    const int CH = (n + 1023) / 1024;
    int beg = t * CH;
    int end = beg + CH < n ? beg + CH : n;

    int sum = 0;
    for (int i = beg; i < end; i++) sum += g_din[i];

    // warp inclusive scan
    int xin = sum;
#pragma unroll
    for (int o = 1; o < 32; o <<= 1) {
        int y = __shfl_up_sync(0xffffffffu, xin, o);
        if (lane >= o) xin += y;
    }
    if (lane == 31) wsums[w] = xin;
    __syncthreads();
    if (w == 0) {
        int v = wsums[lane];
        int y = v;
#pragma unroll
        for (int o = 1; o < 32; o <<= 1) {
            int t2 = __shfl_up_sync(0xffffffffu, y, o);
            if (lane >= o) y += t2;
        }
        wsums[lane] = y - v;   // exclusive
    }
    __syncthreads();

    int run = wsums[w] + (xin - sum);   // exclusive base for this thread
    for (int i = beg; i < end; i++) {
        int d = g_din[i];
        g_off[i] = run;
        run += d;
        g_isi[i] = rsqrtf(fmaxf((float)d, 1.f));
        g_iso[i] = rsqrtf(fmaxf((float)g_dout[i], 1.f));
    }
    if (t == 0) g_off[n] = e;
}

__global__ void fill_csr(const int* __restrict__ src,
                         const int* __restrict__ dst, int e) {
    int i = blockIdx.x * blockDim.x + threadIdx.x;
    if (i < e) {
        int d = dst[i];
        int pos = g_off[d] + atomicAdd(&g_cnt[d], 1);
        g_csr_src[pos] = src[i];
    }
}

// ---- fused layer: gather(64 rows) -> GEMM -> bias -> LayerNorm -> ReLU ----
// Block: 256 threads (8 warps). Each warp gathers 8 rows into smem A tile,
// then all warps do the 64x128 @ 128x128 GEMM with BK=16 B staging.
// hin==nullptr: read g_h1; out==nullptr: write g_h1.
__global__ __launch_bounds__(256)
void gcn_layer(const float* __restrict__ hin,
               const float* __restrict__ W,
               const float* __restrict__ b,
               const float* __restrict__ gamma,
               const float* __restrict__ beta,
               float* __restrict__ out, int n) {
    const float* hp = hin ? hin : g_h1;
    float* op = out ? out : g_h1;

    __shared__ float As[DD][68];    // [k][row], padded (34.8KB)
    __shared__ float Bs[16][128];   // [k][col]  (8KB)

    int tid = threadIdx.x;
    int lane = tid & 31, wid = tid >> 5;
    int rowBase = blockIdx.x * 64;

    // ---- gather phase: warp w handles rows w*8 .. w*8+7 ----
#pragma unroll 1
    for (int j = 0; j < 8; j++) {
        int r = wid * 8 + j;
        int node = rowBase + r;
        float4 acc = make_float4(0.f, 0.f, 0.f, 0.f);
        if (node < n) {
            int beg = g_off[node], end = g_off[node + 1];
            int i = beg;
            for (; i + 8 <= end; i += 8) {
                int s0 = g_csr_src[i + 0], s1 = g_csr_src[i + 1];
                int s2 = g_csr_src[i + 2], s3 = g_csr_src[i + 3];
                int s4 = g_csr_src[i + 4], s5 = g_csr_src[i + 5];
                int s6 = g_csr_src[i + 6], s7 = g_csr_src[i + 7];
                float c0 = g_iso[s0], c1 = g_iso[s1], c2 = g_iso[s2], c3 = g_iso[s3];
                float c4 = g_iso[s4], c5 = g_iso[s5], c6 = g_iso[s6], c7 = g_iso[s7];
                float4 v0 = reinterpret_cast<const float4*>(hp + (size_t)s0 * DD)[lane];
                float4 v1 = reinterpret_cast<const float4*>(hp + (size_t)s1 * DD)[lane];
                float4 v2 = reinterpret_cast<const float4*>(hp + (size_t)s2 * DD)[lane];
                float4 v3 = reinterpret_cast<const float4*>(hp + (size_t)s3 * DD)[lane];
                float4 v4 = reinterpret_cast<const float4*>(hp + (size_t)s4 * DD)[lane];
                float4 v5 = reinterpret_cast<const float4*>(hp + (size_t)s5 * DD)[lane];
                float4 v6 = reinterpret_cast<const float4*>(hp + (size_t)s6 * DD)[lane];
                float4 v7 = reinterpret_cast<const float4*>(hp + (size_t)s7 * DD)[lane];
                acc.x = fmaf(c0, v0.x, fmaf(c1, v1.x, fmaf(c2, v2.x, fmaf(c3, v3.x, acc.x))));
                acc.y = fmaf(c0, v0.y, fmaf(c1, v1.y, fmaf(c2, v2.y, fmaf(c3, v3.y, acc.y))));
                acc.z = fmaf(c0, v0.z, fmaf(c1, v1.z, fmaf(c2, v2.z, fmaf(c3, v3.z, acc.z))));
                acc.w = fmaf(c0, v0.w, fmaf(c1, v1.w, fmaf(c2, v2.w, fmaf(c3, v3.w, acc.w))));
                acc.x = fmaf(c4, v4.x, fmaf(c5, v5.x, fmaf(c6, v6.x, fmaf(c7, v7.x, acc.x))));
                acc.y = fmaf(c4, v4.y, fmaf(c5, v5.y, fmaf(c6, v6.y, fmaf(c7, v7.y, acc.y))));
                acc.z = fmaf(c4, v4.z, fmaf(c5, v5.z, fmaf(c6, v6.z, fmaf(c7, v7.z, acc.z))));
                acc.w = fmaf(c4, v4.w, fmaf(c5, v5.w, fmaf(c6, v6.w, fmaf(c7, v7.w, acc.w))));
            }
            for (; i < end; i++) {
                int s = g_csr_src[i];
                float c = g_iso[s];
                float4 v = reinterpret_cast<const float4*>(hp + (size_t)s * DD)[lane];
                acc.x = fmaf(c, v.x, acc.x);
                acc.y = fmaf(c, v.y, acc.y);
                acc.z = fmaf(c, v.z, acc.z);
                acc.w = fmaf(c, v.w, acc.w);
            }
            float si = g_isi[node];
            acc.x *= si; acc.y *= si; acc.z *= si; acc.w *= si;
        }
        As[4 * lane + 0][r] = acc.x;
        As[4 * lane + 1][r] = acc.y;
        As[4 * lane + 2][r] = acc.z;
        As[4 * lane + 3][r] = acc.w;
    }
    __syncthreads();

    // ---- GEMM phase (R5-proven structure, A already in smem) ----
    int tx = tid & 15;   // col group
    int ty = tid >> 4;   // row group

    float acc[4][8];
#pragma unroll
    for (int i = 0; i < 4; i++)
#pragma unroll
        for (int j = 0; j < 8; j++) acc[i][j] = 0.f;

    for (int k0 = 0; k0 < 128; k0 += 16) {
        // stage B tile: 16 k x 128 cols
#pragma unroll
        for (int u = 0; u < 2; u++) {
            int idx = tid + u * 256;
            int br = idx >> 5;
            int c4 = idx & 31;
            float4 bv = *reinterpret_cast<const float4*>(
                W + (size_t)(k0 + br) * DD + c4 * 4);
            *reinterpret_cast<float4*>(&Bs[br][c4 * 4]) = bv;
        }
        __syncthreads();

#pragma unroll
        for (int kk = 0; kk < 16; kk++) {
            float a0 = As[k0 + kk][ty * 4 + 0];
            float a1 = As[k0 + kk][ty * 4 + 1];
            float a2 = As[k0 + kk][ty * 4 + 2];
            float a3 = As[k0 + kk][ty * 4 + 3];
#pragma unroll
            for (int j = 0; j < 8; j++) {
                float bb = Bs[kk][tx + j * 16];
                acc[0][j] = fmaf(a0, bb, acc[0][j]);
                acc[1][j] = fmaf(a1, bb, acc[1][j]);
                acc[2][j] = fmaf(a2, bb, acc[2][j]);
                acc[3][j] = fmaf(a3, bb, acc[3][j]);
            }
        }
        __syncthreads();
    }

    // ---- epilogue: +bias, LayerNorm over the 128-wide row, ReLU ----
#pragma unroll
    for (int i = 0; i < 4; i++) {
        int grow = rowBase + ty * 4 + i;
        float v[8];
        float s = 0.f, s2 = 0.f;
#pragma unroll
        for (int j = 0; j < 8; j++) {
            int col = tx + j * 16;
            v[j] = acc[i][j] + b[col];
            s += v[j];
            s2 += v[j] * v[j];
        }
        // reduce across the 16 lanes that share this row
#pragma unroll
        for (int m = 1; m < 16; m <<= 1) {
            s  += __shfl_xor_sync(0xffffffffu, s,  m);
            s2 += __shfl_xor_sync(0xffffffffu, s2, m);
        }
        float mu  = s * (1.f / 128.f);
        float var = s2 * (1.f / 128.f) - mu * mu;
        float inv = rsqrtf(var + LN_EPS);
        if (grow < n) {
#pragma unroll
            for (int j = 0; j < 8; j++) {
                int col = tx + j * 16;
                float y = (v[j] - mu) * inv * gamma[col] + beta[col];
                op[(size_t)grow * DD + col] = fmaxf(y, 0.f);
            }
        }
    }
}

extern "C" void kernel_launch(void* const* d_in, const int* in_sizes, int n_in,
                              void* d_out, int out_size) {
    const float* features = (const float*)d_in[0];
    const int*   src      = (const int*)d_in[1];
    const int*   dst      = (const int*)d_in[2];
    const float* W1  = (const float*)d_in[3];
    const float* b1  = (const float*)d_in[4];
    const float* g1  = (const float*)d_in[5];
    const float* be1 = (const float*)d_in[6];
    const float* W2  = (const float*)d_in[7];
    const float* b2  = (const float*)d_in[8];
    const float* g2  = (const float*)d_in[9];
    const float* be2 = (const float*)d_in[10];
    float* out = (float*)d_out;

    int n = in_sizes[0] / DD;   // 50000
    int e = in_sizes[1];        // 800000

    int nBlocks    = (n + 255) / 256;
    int eBlocks    = (e + 255) / 256;
    int layerBlocks = (n + 63) / 64;

    // ---- CSR build (once, reused by both layers): 4 launches ----
    zero_counts<<<nBlocks, 256>>>(n);
    deg_count<<<eBlocks, 256>>>(src, dst, e);
    scan_finalize<<<1, 1024>>>(n, e);
    fill_csr<<<eBlocks, 256>>>(src, dst, e);

    // ---- fused layers: 2 launches ----
    gcn_layer<<<layerBlocks, 256>>>(features, W1, b1, g1, be1, nullptr, n);
    gcn_layer<<<layerBlocks, 256>>>(nullptr,  W2, b2, g2, be2, out, n);
}

// round 12
// speedup vs baseline: 1.0527x; 1.0527x over previous
#include <cuda_runtime.h>
#include <cstdint>

#define NNODES 50000
#define EDGES  800000
#define DD 128
#define LN_EPS 1e-5f

// ---- scratch (device globals; no allocation allowed) ----
__device__ float g_agg[(size_t)NNODES * DD];   // SpMM output
__device__ float g_h1[(size_t)NNODES * DD];    // layer-1 output
__device__ float g_iso[NNODES];
__device__ float g_isi[NNODES];
__device__ int   g_din[NNODES];
__device__ int   g_dout[NNODES];
__device__ int   g_cnt[NNODES];
__device__ int   g_off[NNODES + 1];
__device__ int   g_csr_src[EDGES];

// ---- CSR build ----
__global__ void zero_counts(int n) {
    int i = blockIdx.x * blockDim.x + threadIdx.x;
    if (i < n) { g_din[i] = 0; g_dout[i] = 0; g_cnt[i] = 0; }
}

__global__ void deg_count(const int* __restrict__ src,
                          const int* __restrict__ dst, int e) {
    int i = blockIdx.x * blockDim.x + threadIdx.x;
    if (i < e) {
        atomicAdd(&g_dout[src[i]], 1);
        atomicAdd(&g_din[dst[i]], 1);
    }
}

// ---- single-block scan over g_din + finalize offsets/iso/isi ----
__global__ void scan_finalize(int n, int e) {
    __shared__ int wsums[32];
    int t = threadIdx.x;
    int lane = t & 31, w = t >> 5;
    const int CH = (n + 1023) / 1024;
    int beg = t * CH;
    int end = beg + CH < n ? beg + CH : n;

    int sum = 0;
    for (int i = beg; i < end; i++) sum += g_din[i];

    int xin = sum;
#pragma unroll
    for (int o = 1; o < 32; o <<= 1) {
        int y = __shfl_up_sync(0xffffffffu, xin, o);
        if (lane >= o) xin += y;
    }
    if (lane == 31) wsums[w] = xin;
    __syncthreads();
    if (w == 0) {
        int v = wsums[lane];
        int y = v;
#pragma unroll
        for (int o = 1; o < 32; o <<= 1) {
            int t2 = __shfl_up_sync(0xffffffffu, y, o);
            if (lane >= o) y += t2;
        }
        wsums[lane] = y - v;   // exclusive
    }
    __syncthreads();

    int run = wsums[w] + (xin - sum);   // exclusive base for this thread
    for (int i = beg; i < end; i++) {
        int d = g_din[i];
        g_off[i] = run;
        run += d;
        g_isi[i] = rsqrtf(fmaxf((float)d, 1.f));
        g_iso[i] = rsqrtf(fmaxf((float)g_dout[i], 1.f));
    }
    if (t == 0) g_off[n] = e;
}

__global__ void fill_csr(const int* __restrict__ src,
                         const int* __restrict__ dst, int e) {
    int i = blockIdx.x * blockDim.x + threadIdx.x;
    if (i < e) {
        int d = dst[i];
        int pos = g_off[d] + atomicAdd(&g_cnt[d], 1);
        g_csr_src[pos] = src[i];
    }
}

// ---- pull-model SpMM: one warp per dst node, register accumulation ----
__global__ void gather_spmm(const float* __restrict__ h, int n) {
    const float* hp = h ? h : g_h1;
    int w = (blockIdx.x * blockDim.x + threadIdx.x) >> 5;
    int lane = threadIdx.x & 31;
    if (w >= n) return;
    int beg = g_off[w], end = g_off[w + 1];
    float4 acc = make_float4(0.f, 0.f, 0.f, 0.f);

    int i = beg;
    for (; i + 8 <= end; i += 8) {
        int s0 = g_csr_src[i + 0], s1 = g_csr_src[i + 1];
        int s2 = g_csr_src[i + 2], s3 = g_csr_src[i + 3];
        int s4 = g_csr_src[i + 4], s5 = g_csr_src[i + 5];
        int s6 = g_csr_src[i + 6], s7 = g_csr_src[i + 7];
        float c0 = g_iso[s0], c1 = g_iso[s1], c2 = g_iso[s2], c3 = g_iso[s3];
        float c4 = g_iso[s4], c5 = g_iso[s5], c6 = g_iso[s6], c7 = g_iso[s7];
        float4 v0 = reinterpret_cast<const float4*>(hp + (size_t)s0 * DD)[lane];
        float4 v1 = reinterpret_cast<const float4*>(hp + (size_t)s1 * DD)[lane];
        float4 v2 = reinterpret_cast<const float4*>(hp + (size_t)s2 * DD)[lane];
        float4 v3 = reinterpret_cast<const float4*>(hp + (size_t)s3 * DD)[lane];
        float4 v4 = reinterpret_cast<const float4*>(hp + (size_t)s4 * DD)[lane];
        float4 v5 = reinterpret_cast<const float4*>(hp + (size_t)s5 * DD)[lane];
        float4 v6 = reinterpret_cast<const float4*>(hp + (size_t)s6 * DD)[lane];
        float4 v7 = reinterpret_cast<const float4*>(hp + (size_t)s7 * DD)[lane];
        acc.x = fmaf(c0, v0.x, fmaf(c1, v1.x, fmaf(c2, v2.x, fmaf(c3, v3.x, acc.x))));
        acc.y = fmaf(c0, v0.y, fmaf(c1, v1.y, fmaf(c2, v2.y, fmaf(c3, v3.y, acc.y))));
        acc.z = fmaf(c0, v0.z, fmaf(c1, v1.z, fmaf(c2, v2.z, fmaf(c3, v3.z, acc.z))));
        acc.w = fmaf(c0, v0.w, fmaf(c1, v1.w, fmaf(c2, v2.w, fmaf(c3, v3.w, acc.w))));
        acc.x = fmaf(c4, v4.x, fmaf(c5, v5.x, fmaf(c6, v6.x, fmaf(c7, v7.x, acc.x))));
        acc.y = fmaf(c4, v4.y, fmaf(c5, v5.y, fmaf(c6, v6.y, fmaf(c7, v7.y, acc.y))));
        acc.z = fmaf(c4, v4.z, fmaf(c5, v5.z, fmaf(c6, v6.z, fmaf(c7, v7.z, acc.z))));
        acc.w = fmaf(c4, v4.w, fmaf(c5, v5.w, fmaf(c6, v6.w, fmaf(c7, v7.w, acc.w))));
    }
    for (; i < end; i++) {
        int s = g_csr_src[i];
        float c = g_iso[s];
        float4 v = reinterpret_cast<const float4*>(hp + (size_t)s * DD)[lane];
        acc.x = fmaf(c, v.x, acc.x);
        acc.y = fmaf(c, v.y, acc.y);
        acc.z = fmaf(c, v.z, acc.z);
        acc.w = fmaf(c, v.w, acc.w);
    }
    float si = g_isi[w];
    acc.x *= si; acc.y *= si; acc.z *= si; acc.w *= si;
    reinterpret_cast<float4*>(g_agg + (size_t)w * DD)[lane] = acc;
}

// ---- fused agg @ W + b -> LayerNorm -> ReLU (R5-proven) ----
// Block: 256 threads (16x16), tile 64 rows x 128 cols, BK=16.
// out==nullptr means write to g_h1.
__global__ __launch_bounds__(256)
void gemm_ln_relu(const float* __restrict__ W,
                  const float* __restrict__ b,
                  const float* __restrict__ gamma,
                  const float* __restrict__ beta,
                  float* __restrict__ out, int n) {
    float* op = out ? out : g_h1;

    __shared__ float As[16][68];   // [k][row], padded
    __shared__ float Bs[16][128];  // [k][col]

    int tid = threadIdx.x;
    int tx = tid & 15;   // col group
    int ty = tid >> 4;   // row group
    int rowBase = blockIdx.x * 64;

    float acc[4][8];
#pragma unroll
    for (int i = 0; i < 4; i++)
#pragma unroll
        for (int j = 0; j < 8; j++) acc[i][j] = 0.f;

    int r = tid >> 2;      // 0..63
    int q = tid & 3;       // 0..3
    int grow_ld = rowBase + r;

    for (int k0 = 0; k0 < 128; k0 += 16) {
        float4 av = make_float4(0.f, 0.f, 0.f, 0.f);
        if (grow_ld < n)
            av = *reinterpret_cast<const float4*>(
                g_agg + (size_t)grow_ld * DD + k0 + q * 4);
        As[q * 4 + 0][r] = av.x;
        As[q * 4 + 1][r] = av.y;
        As[q * 4 + 2][r] = av.z;
        As[q * 4 + 3][r] = av.w;

#pragma unroll
        for (int u = 0; u < 2; u++) {
            int idx = tid + u * 256;
            int br = idx >> 5;
            int c4 = idx & 31;
            float4 bv = *reinterpret_cast<const float4*>(
                W + (size_t)(k0 + br) * DD + c4 * 4);
            *reinterpret_cast<float4*>(&Bs[br][c4 * 4]) = bv;
        }
        __syncthreads();

#pragma unroll
        for (int kk = 0; kk < 16; kk++) {
            float a0 = As[kk][ty * 4 + 0];
            float a1 = As[kk][ty * 4 + 1];
            float a2 = As[kk][ty * 4 + 2];
            float a3 = As[kk][ty * 4 + 3];
#pragma unroll
            for (int j = 0; j < 8; j++) {
                float bb = Bs[kk][tx + j * 16];
                acc[0][j] = fmaf(a0, bb, acc[0][j]);
                acc[1][j] = fmaf(a1, bb, acc[1][j]);
                acc[2][j] = fmaf(a2, bb, acc[2][j]);
                acc[3][j] = fmaf(a3, bb, acc[3][j]);
            }
        }
        __syncthreads();
    }

    // epilogue: +bias, LayerNorm over the 128-wide row, ReLU
#pragma unroll
    for (int i = 0; i < 4; i++) {
        int grow = rowBase + ty * 4 + i;
        float v[8];
        float s = 0.f, s2 = 0.f;
#pragma unroll
        for (int j = 0; j < 8; j++) {
            int col = tx + j * 16;
            v[j] = acc[i][j] + b[col];
            s += v[j];
            s2 += v[j] * v[j];
        }
#pragma unroll
        for (int m = 1; m < 16; m <<= 1) {
            s  += __shfl_xor_sync(0xffffffffu, s,  m);
            s2 += __shfl_xor_sync(0xffffffffu, s2, m);
        }
        float mu  = s * (1.f / 128.f);
        float var = s2 * (1.f / 128.f) - mu * mu;
        float inv = rsqrtf(var + LN_EPS);
        if (grow < n) {
#pragma unroll
            for (int j = 0; j < 8; j++) {
                int col = tx + j * 16;
                float y = (v[j] - mu) * inv * gamma[col] + beta[col];
                op[(size_t)grow * DD + col] = fmaxf(y, 0.f);
            }
        }
    }
}

extern "C" void kernel_launch(void* const* d_in, const int* in_sizes, int n_in,
                              void* d_out, int out_size) {
    const float* features = (const float*)d_in[0];
    const int*   src      = (const int*)d_in[1];
    const int*   dst      = (const int*)d_in[2];
    const float* W1  = (const float*)d_in[3];
    const float* b1  = (const float*)d_in[4];
    const float* g1  = (const float*)d_in[5];
    const float* be1 = (const float*)d_in[6];
    const float* W2  = (const float*)d_in[7];
    const float* b2  = (const float*)d_in[8];
    const float* g2  = (const float*)d_in[9];
    const float* be2 = (const float*)d_in[10];
    float* out = (float*)d_out;

    int n = in_sizes[0] / DD;   // 50000
    int e = in_sizes[1];        // 800000

    int nBlocks    = (n + 255) / 256;
    int eBlocks    = (e + 255) / 256;
    int gathBlocks = (int)(((long long)n * 32 + 255) / 256);
    int gemmBlocks = (n + 63) / 64;

    // ---- CSR build (once, reused by both layers): 4 launches ----
    zero_counts<<<nBlocks, 256>>>(n);
    deg_count<<<eBlocks, 256>>>(src, dst, e);
    scan_finalize<<<1, 1024>>>(n, e);
    fill_csr<<<eBlocks, 256>>>(src, dst, e);

    // ---- layer 1 ----
    gather_spmm<<<gathBlocks, 256>>>(features, n);
    gemm_ln_relu<<<gemmBlocks, 256>>>(W1, b1, g1, be1, nullptr, n);

    // ---- layer 2 ----
    gather_spmm<<<gathBlocks, 256>>>(nullptr, n);
    gemm_ln_relu<<<gemmBlocks, 256>>>(W2, b2, g2, be2, out, n);
}

// round 13
// speedup vs baseline: 1.6614x; 1.5782x over previous
#include <cuda_runtime.h>
#include <cstdint>

#define NNODES 50000
#define EDGES  800000
#define DD 128
#define LN_EPS 1e-5f

// ---- scratch (device globals; no allocation allowed) ----
__device__ float g_agg[(size_t)NNODES * DD];   // SpMM output
__device__ float g_h1[(size_t)NNODES * DD];    // layer-1 output
__device__ float g_iso[NNODES];
__device__ float g_isi[NNODES];
__device__ int   g_din[NNODES];
__device__ int   g_dout[NNODES];
__device__ int   g_cnt[NNODES];
__device__ int   g_scan[NNODES];
__device__ int   g_bsum[64];
__device__ int   g_off[NNODES + 1];
__device__ int   g_csr_src[EDGES];

// ---- CSR build ----
__global__ void zero_counts(int n) {
    int i = blockIdx.x * blockDim.x + threadIdx.x;
    if (i < n) { g_din[i] = 0; g_dout[i] = 0; g_cnt[i] = 0; }
}

__global__ void deg_count(const int* __restrict__ src,
                          const int* __restrict__ dst, int e) {
    int i = blockIdx.x * blockDim.x + threadIdx.x;
    if (i < e) {
        atomicAdd(&g_dout[src[i]], 1);
        atomicAdd(&g_din[dst[i]], 1);
    }
}

__global__ void scan_blocks(int n) {
    __shared__ int sh[1024];
    int gid = blockIdx.x * 1024 + threadIdx.x;
    int v = (gid < n) ? g_din[gid] : 0;
    sh[threadIdx.x] = v;
    __syncthreads();
#pragma unroll
    for (int off = 1; off < 1024; off <<= 1) {
        int t = (threadIdx.x >= off) ? sh[threadIdx.x - off] : 0;
        __syncthreads();
        sh[threadIdx.x] += t;
        __syncthreads();
    }
    if (gid < n) g_scan[gid] = sh[threadIdx.x];          // inclusive
    if (threadIdx.x == 1023) g_bsum[blockIdx.x] = sh[1023];
}

__global__ void scan_partials(int nb) {
    int t = threadIdx.x;
    int v = (t < nb) ? g_bsum[t] : 0;
    int lane = t & 31, w = t >> 5;
    int x = v;
#pragma unroll
    for (int o = 1; o < 32; o <<= 1) {
        int y = __shfl_up_sync(0xffffffffu, x, o);
        if (lane >= o) x += y;
    }
    __shared__ int wsum[2];
    if (lane == 31) wsum[w] = x;
    __syncthreads();
    if (w == 1) x += wsum[0];
    if (t < nb) g_bsum[t] = x - v;                       // exclusive
}

__global__ void finalize_off(int n, int e) {
    int gid = blockIdx.x * blockDim.x + threadIdx.x;
    if (gid < n) {
        int incl = g_scan[gid] + g_bsum[gid >> 10];
        g_off[gid] = incl - g_din[gid];
        g_iso[gid] = rsqrtf(fmaxf((float)g_dout[gid], 1.f));
        g_isi[gid] = rsqrtf(fmaxf((float)g_din[gid], 1.f));
    }
    if (gid == 0) g_off[n] = e;
}

__global__ void fill_csr(const int* __restrict__ src,
                         const int* __restrict__ dst, int e) {
    int i = blockIdx.x * blockDim.x + threadIdx.x;
    if (i < e) {
        int d = dst[i];
        int pos = g_off[d] + atomicAdd(&g_cnt[d], 1);
        g_csr_src[pos] = src[i];
    }
}

// ---- pull-model SpMM: one warp per dst node, register accumulation ----
__global__ void gather_spmm(const float* __restrict__ h, int n) {
    const float* hp = h ? h : g_h1;
    int w = (blockIdx.x * blockDim.x + threadIdx.x) >> 5;
    int lane = threadIdx.x & 31;
    if (w >= n) return;
    int beg = g_off[w], end = g_off[w + 1];
    float4 acc = make_float4(0.f, 0.f, 0.f, 0.f);

    int i = beg;
    for (; i + 8 <= end; i += 8) {
        int s0 = g_csr_src[i + 0], s1 = g_csr_src[i + 1];
        int s2 = g_csr_src[i + 2], s3 = g_csr_src[i + 3];
        int s4 = g_csr_src[i + 4], s5 = g_csr_src[i + 5];
        int s6 = g_csr_src[i + 6], s7 = g_csr_src[i + 7];
        float c0 = g_iso[s0], c1 = g_iso[s1], c2 = g_iso[s2], c3 = g_iso[s3];
        float c4 = g_iso[s4], c5 = g_iso[s5], c6 = g_iso[s6], c7 = g_iso[s7];
        float4 v0 = reinterpret_cast<const float4*>(hp + (size_t)s0 * DD)[lane];
        float4 v1 = reinterpret_cast<const float4*>(hp + (size_t)s1 * DD)[lane];
        float4 v2 = reinterpret_cast<const float4*>(hp + (size_t)s2 * DD)[lane];
        float4 v3 = reinterpret_cast<const float4*>(hp + (size_t)s3 * DD)[lane];
        float4 v4 = reinterpret_cast<const float4*>(hp + (size_t)s4 * DD)[lane];
        float4 v5 = reinterpret_cast<const float4*>(hp + (size_t)s5 * DD)[lane];
        float4 v6 = reinterpret_cast<const float4*>(hp + (size_t)s6 * DD)[lane];
        float4 v7 = reinterpret_cast<const float4*>(hp + (size_t)s7 * DD)[lane];
        acc.x = fmaf(c0, v0.x, fmaf(c1, v1.x, fmaf(c2, v2.x, fmaf(c3, v3.x, acc.x))));
        acc.y = fmaf(c0, v0.y, fmaf(c1, v1.y, fmaf(c2, v2.y, fmaf(c3, v3.y, acc.y))));
        acc.z = fmaf(c0, v0.z, fmaf(c1, v1.z, fmaf(c2, v2.z, fmaf(c3, v3.z, acc.z))));
        acc.w = fmaf(c0, v0.w, fmaf(c1, v1.w, fmaf(c2, v2.w, fmaf(c3, v3.w, acc.w))));
        acc.x = fmaf(c4, v4.x, fmaf(c5, v5.x, fmaf(c6, v6.x, fmaf(c7, v7.x, acc.x))));
        acc.y = fmaf(c4, v4.y, fmaf(c5, v5.y, fmaf(c6, v6.y, fmaf(c7, v7.y, acc.y))));
        acc.z = fmaf(c4, v4.z, fmaf(c5, v5.z, fmaf(c6, v6.z, fmaf(c7, v7.z, acc.z))));
        acc.w = fmaf(c4, v4.w, fmaf(c5, v5.w, fmaf(c6, v6.w, fmaf(c7, v7.w, acc.w))));
    }
    for (; i < end; i++) {
        int s = g_csr_src[i];
        float c = g_iso[s];
        float4 v = reinterpret_cast<const float4*>(hp + (size_t)s * DD)[lane];
        acc.x = fmaf(c, v.x, acc.x);
        acc.y = fmaf(c, v.y, acc.y);
        acc.z = fmaf(c, v.z, acc.z);
        acc.w = fmaf(c, v.w, acc.w);
    }
    float si = g_isi[w];
    acc.x *= si; acc.y *= si; acc.z *= si; acc.w *= si;
    reinterpret_cast<float4*>(g_agg + (size_t)w * DD)[lane] = acc;
}

// ---- fused agg @ W + b -> LayerNorm -> ReLU (R5-proven) ----
// Block: 256 threads (16x16), tile 64 rows x 128 cols, BK=16.
// out==nullptr means write to g_h1.
__global__ __launch_bounds__(256)
void gemm_ln_relu(const float* __restrict__ W,
                  const float* __restrict__ b,
                  const float* __restrict__ gamma,
                  const float* __restrict__ beta,
                  float* __restrict__ out, int n) {
    float* op = out ? out : g_h1;

    __shared__ float As[16][68];   // [k][row], padded
    __shared__ float Bs[16][128];  // [k][col]

    int tid = threadIdx.x;
    int tx = tid & 15;   // col group
    int ty = tid >> 4;   // row group
    int rowBase = blockIdx.x * 64;

    float acc[4][8];
#pragma unroll
    for (int i = 0; i < 4; i++)
#pragma unroll
        for (int j = 0; j < 8; j++) acc[i][j] = 0.f;

    int r = tid >> 2;      // 0..63
    int q = tid & 3;       // 0..3
    int grow_ld = rowBase + r;

    for (int k0 = 0; k0 < 128; k0 += 16) {
        float4 av = make_float4(0.f, 0.f, 0.f, 0.f);
        if (grow_ld < n)
            av = *reinterpret_cast<const float4*>(
                g_agg + (size_t)grow_ld * DD + k0 + q * 4);
        As[q * 4 + 0][r] = av.x;
        As[q * 4 + 1][r] = av.y;
        As[q * 4 + 2][r] = av.z;
        As[q * 4 + 3][r] = av.w;

#pragma unroll
        for (int u = 0; u < 2; u++) {
            int idx = tid + u * 256;
            int br = idx >> 5;
            int c4 = idx & 31;
            float4 bv = *reinterpret_cast<const float4*>(
                W + (size_t)(k0 + br) * DD + c4 * 4);
            *reinterpret_cast<float4*>(&Bs[br][c4 * 4]) = bv;
        }
        __syncthreads();

#pragma unroll
        for (int kk = 0; kk < 16; kk++) {
            float a0 = As[kk][ty * 4 + 0];
            float a1 = As[kk][ty * 4 + 1];
            float a2 = As[kk][ty * 4 + 2];
            float a3 = As[kk][ty * 4 + 3];
#pragma unroll
            for (int j = 0; j < 8; j++) {
                float bb = Bs[kk][tx + j * 16];
                acc[0][j] = fmaf(a0, bb, acc[0][j]);
                acc[1][j] = fmaf(a1, bb, acc[1][j]);
                acc[2][j] = fmaf(a2, bb, acc[2][j]);
                acc[3][j] = fmaf(a3, bb, acc[3][j]);
            }
        }
        __syncthreads();
    }

    // epilogue: +bias, LayerNorm over the 128-wide row, ReLU
#pragma unroll
    for (int i = 0; i < 4; i++) {
        int grow = rowBase + ty * 4 + i;
        float v[8];
        float s = 0.f, s2 = 0.f;
#pragma unroll
        for (int j = 0; j < 8; j++) {
            int col = tx + j * 16;
            v[j] = acc[i][j] + b[col];
            s += v[j];
            s2 += v[j] * v[j];
        }
#pragma unroll
        for (int m = 1; m < 16; m <<= 1) {
            s  += __shfl_xor_sync(0xffffffffu, s,  m);
            s2 += __shfl_xor_sync(0xffffffffu, s2, m);
        }
        float mu  = s * (1.f / 128.f);
        float var = s2 * (1.f / 128.f) - mu * mu;
        float inv = rsqrtf(var + LN_EPS);
        if (grow < n) {
#pragma unroll
            for (int j = 0; j < 8; j++) {
                int col = tx + j * 16;
                float y = (v[j] - mu) * inv * gamma[col] + beta[col];
                op[(size_t)grow * DD + col] = fmaxf(y, 0.f);
            }
        }
    }
}

extern "C" void kernel_launch(void* const* d_in, const int* in_sizes, int n_in,
                              void* d_out, int out_size) {
    const float* features = (const float*)d_in[0];
    const int*   src      = (const int*)d_in[1];
    const int*   dst      = (const int*)d_in[2];
    const float* W1  = (const float*)d_in[3];
    const float* b1  = (const float*)d_in[4];
    const float* g1  = (const float*)d_in[5];
    const float* be1 = (const float*)d_in[6];
    const float* W2  = (const float*)d_in[7];
    const float* b2  = (const float*)d_in[8];
    const float* g2  = (const float*)d_in[9];
    const float* be2 = (const float*)d_in[10];
    float* out = (float*)d_out;

    int n = in_sizes[0] / DD;   // 50000
    int e = in_sizes[1];        // 800000

    int nBlocks    = (n + 255) / 256;
    int eBlocks    = (e + 255) / 256;
    int scanBlocks = (n + 1023) / 1024;
    int gathBlocks = (int)(((long long)n * 32 + 255) / 256);
    int gemmBlocks = (n + 63) / 64;

    // ---- CSR build (once, reused by both layers) ----
    zero_counts<<<nBlocks, 256>>>(n);
    deg_count<<<eBlocks, 256>>>(src, dst, e);
    scan_blocks<<<scanBlocks, 1024>>>(n);
    scan_partials<<<1, 64>>>(scanBlocks);
    finalize_off<<<nBlocks, 256>>>(n, e);
    fill_csr<<<eBlocks, 256>>>(src, dst, e);

    // ---- layer 1 ----
    gather_spmm<<<gathBlocks, 256>>>(features, n);
    gemm_ln_relu<<<gemmBlocks, 256>>>(W1, b1, g1, be1, nullptr, n);

    // ---- layer 2 ----
    gather_spmm<<<gathBlocks, 256>>>(nullptr, n);
    gemm_ln_relu<<<gemmBlocks, 256>>>(W2, b2, g2, be2, out, n);
}

// round 14
// speedup vs baseline: 1.7695x; 1.0650x over previous
#include <cuda_runtime.h>
#include <cstdint>

#define NNODES 50000
#define EDGES  800000
#define DD 128
#define LN_EPS 1e-5f

// ---- scratch (device globals; no allocation allowed) ----
__device__ float g_agg[(size_t)NNODES * DD];   // t = (X @ W) * iso[row]
__device__ float g_h1[(size_t)NNODES * DD];    // layer-1 output
__device__ float g_iso[NNODES];
__device__ float g_isi[NNODES];
__device__ int   g_din[NNODES];
__device__ int   g_dout[NNODES];
__device__ int   g_cnt[NNODES];
__device__ int   g_scan[NNODES];
__device__ int   g_bsum[64];
__device__ int   g_off[NNODES + 1];
__device__ int   g_csr_src[EDGES];

// ---- CSR build ----
__global__ void zero_counts(int n) {
    int i = blockIdx.x * blockDim.x + threadIdx.x;
    if (i < n) { g_din[i] = 0; g_dout[i] = 0; g_cnt[i] = 0; }
}

__global__ void deg_count(const int* __restrict__ src,
                          const int* __restrict__ dst, int e) {
    int i = blockIdx.x * blockDim.x + threadIdx.x;
    if (i < e) {
        atomicAdd(&g_dout[src[i]], 1);
        atomicAdd(&g_din[dst[i]], 1);
    }
}

__global__ void scan_blocks(int n) {
    __shared__ int sh[1024];
    int gid = blockIdx.x * 1024 + threadIdx.x;
    int v = (gid < n) ? g_din[gid] : 0;
    sh[threadIdx.x] = v;
    __syncthreads();
#pragma unroll
    for (int off = 1; off < 1024; off <<= 1) {
        int t = (threadIdx.x >= off) ? sh[threadIdx.x - off] : 0;
        __syncthreads();
        sh[threadIdx.x] += t;
        __syncthreads();
    }
    if (gid < n) g_scan[gid] = sh[threadIdx.x];          // inclusive
    if (threadIdx.x == 1023) g_bsum[blockIdx.x] = sh[1023];
}

// finalize with the partials-scan folded in (each block redundantly scans <=64 bsums)
__global__ void finalize_off(int n, int e, int nb) {
    __shared__ int sb[64];
    __shared__ int w0tot;
    int t = threadIdx.x;
    if (t < 64) {
        int v = (t < nb) ? g_bsum[t] : 0;
        int lane = t & 31;
        int x = v;
#pragma unroll
        for (int o = 1; o < 32; o <<= 1) {
            int y = __shfl_up_sync(0xffffffffu, x, o);
            if (lane >= o) x += y;
        }
        if (t == 31) w0tot = x;
        sb[t] = x - v;   // exclusive within warp
    }
    __syncthreads();
    if (t >= 32 && t < 64) sb[t] += w0tot;
    __syncthreads();

    int gid = blockIdx.x * blockDim.x + t;
    if (gid < n) {
        int incl = g_scan[gid] + sb[gid >> 10];
        g_off[gid] = incl - g_din[gid];
        g_iso[gid] = rsqrtf(fmaxf((float)g_dout[gid], 1.f));
        g_isi[gid] = rsqrtf(fmaxf((float)g_din[gid], 1.f));
    }
    if (gid == 0) g_off[n] = e;
}

// ---- GEMM body: g_agg[row] = (X[row] @ W) * iso[row]  (R5-proven tile) ----
// Block: 256 threads, tile 64 rows x 128 cols, BK=16.
__device__ __forceinline__ void gemm_body(const float* __restrict__ X,
                                          const float* __restrict__ W,
                                          int n, int bid, int tid) {
    __shared__ float As[16][68];   // [k][row], padded
    __shared__ float Bs[16][128];  // [k][col]

    int tx = tid & 15;
    int ty = tid >> 4;
    int rowBase = bid * 64;

    float acc[4][8];
#pragma unroll
    for (int i = 0; i < 4; i++)
#pragma unroll
        for (int j = 0; j < 8; j++) acc[i][j] = 0.f;

    int r = tid >> 2;
    int q = tid & 3;
    int grow_ld = rowBase + r;

    for (int k0 = 0; k0 < 128; k0 += 16) {
        float4 av = make_float4(0.f, 0.f, 0.f, 0.f);
        if (grow_ld < n)
            av = *reinterpret_cast<const float4*>(
                X + (size_t)grow_ld * DD + k0 + q * 4);
        As[q * 4 + 0][r] = av.x;
        As[q * 4 + 1][r] = av.y;
        As[q * 4 + 2][r] = av.z;
        As[q * 4 + 3][r] = av.w;

#pragma unroll
        for (int u = 0; u < 2; u++) {
            int idx = tid + u * 256;
            int br = idx >> 5;
            int c4 = idx & 31;
            float4 bv = *reinterpret_cast<const float4*>(
                W + (size_t)(k0 + br) * DD + c4 * 4);
            *reinterpret_cast<float4*>(&Bs[br][c4 * 4]) = bv;
        }
        __syncthreads();

#pragma unroll
        for (int kk = 0; kk < 16; kk++) {
            float a0 = As[kk][ty * 4 + 0];
            float a1 = As[kk][ty * 4 + 1];
            float a2 = As[kk][ty * 4 + 2];
            float a3 = As[kk][ty * 4 + 3];
#pragma unroll
            for (int j = 0; j < 8; j++) {
                float bb = Bs[kk][tx + j * 16];
                acc[0][j] = fmaf(a0, bb, acc[0][j]);
                acc[1][j] = fmaf(a1, bb, acc[1][j]);
                acc[2][j] = fmaf(a2, bb, acc[2][j]);
                acc[3][j] = fmaf(a3, bb, acc[3][j]);
            }
        }
        __syncthreads();
    }

    // epilogue: scale row by iso, store raw t
#pragma unroll
    for (int i = 0; i < 4; i++) {
        int grow = rowBase + ty * 4 + i;
        if (grow < n) {
            float sc = g_iso[grow];
#pragma unroll
            for (int j = 0; j < 8; j++)
                g_agg[(size_t)grow * DD + tx + j * 16] = acc[i][j] * sc;
        }
    }
}

// ---- heterogeneous kernel: GEMM1 (blocks [0,gb)) + fill_csr (blocks [gb,..)) ----
__global__ __launch_bounds__(256)
void fill_gemm1(const int* __restrict__ src, const int* __restrict__ dst, int e,
                const float* __restrict__ X, const float* __restrict__ W,
                int n, int gb) {
    if ((int)blockIdx.x < gb) {
        gemm_body(X, W, n, blockIdx.x, threadIdx.x);
    } else {
        int i = (blockIdx.x - gb) * 256 + threadIdx.x;
        if (i < e) {
            int d = dst[i];
            int pos = g_off[d] + atomicAdd(&g_cnt[d], 1);
            g_csr_src[pos] = src[i];
        }
    }
}

// ---- standalone GEMM (layer 2): X==nullptr -> g_h1 ----
__global__ __launch_bounds__(256)
void gemm_t(const float* __restrict__ Xin, const float* __restrict__ W, int n) {
    const float* X = Xin ? Xin : g_h1;
    gemm_body(X, W, n, blockIdx.x, threadIdx.x);
}

// ---- gather + isi + bias + LayerNorm + ReLU: one warp per dst node ----
// reads t from g_agg (rows pre-scaled by iso); out==nullptr -> g_h1.
__global__ void gather_ln(const float* __restrict__ b,
                          const float* __restrict__ gamma,
                          const float* __restrict__ beta,
                          float* __restrict__ out, int n) {
    float* op = out ? out : g_h1;
    int w = (blockIdx.x * blockDim.x + threadIdx.x) >> 5;
    int lane = threadIdx.x & 31;
    if (w >= n) return;
    int beg = g_off[w], end = g_off[w + 1];
    float4 acc = make_float4(0.f, 0.f, 0.f, 0.f);

    int i = beg;
    for (; i + 8 <= end; i += 8) {
        int s0 = g_csr_src[i + 0], s1 = g_csr_src[i + 1];
        int s2 = g_csr_src[i + 2], s3 = g_csr_src[i + 3];
        int s4 = g_csr_src[i + 4], s5 = g_csr_src[i + 5];
        int s6 = g_csr_src[i + 6], s7 = g_csr_src[i + 7];
        float4 v0 = reinterpret_cast<const float4*>(g_agg + (size_t)s0 * DD)[lane];
        float4 v1 = reinterpret_cast<const float4*>(g_agg + (size_t)s1 * DD)[lane];
        float4 v2 = reinterpret_cast<const float4*>(g_agg + (size_t)s2 * DD)[lane];
        float4 v3 = reinterpret_cast<const float4*>(g_agg + (size_t)s3 * DD)[lane];
        float4 v4 = reinterpret_cast<const float4*>(g_agg + (size_t)s4 * DD)[lane];
        float4 v5 = reinterpret_cast<const float4*>(g_agg + (size_t)s5 * DD)[lane];
        float4 v6 = reinterpret_cast<const float4*>(g_agg + (size_t)s6 * DD)[lane];
        float4 v7 = reinterpret_cast<const float4*>(g_agg + (size_t)s7 * DD)[lane];
        acc.x += (v0.x + v1.x) + (v2.x + v3.x) + (v4.x + v5.x) + (v6.x + v7.x);
        acc.y += (v0.y + v1.y) + (v2.y + v3.y) + (v4.y + v5.y) + (v6.y + v7.y);
        acc.z += (v0.z + v1.z) + (v2.z + v3.z) + (v4.z + v5.z) + (v6.z + v7.z);
        acc.w += (v0.w + v1.w) + (v2.w + v3.w) + (v4.w + v5.w) + (v6.w + v7.w);
    }
    for (; i < end; i++) {
        int s = g_csr_src[i];
        float4 v = reinterpret_cast<const float4*>(g_agg + (size_t)s * DD)[lane];
        acc.x += v.x; acc.y += v.y; acc.z += v.z; acc.w += v.w;
    }

    float si = g_isi[w];
    float4 bb = reinterpret_cast<const float4*>(b)[lane];
    float v0 = fmaf(acc.x, si, bb.x);
    float v1 = fmaf(acc.y, si, bb.y);
    float v2 = fmaf(acc.z, si, bb.z);
    float v3 = fmaf(acc.w, si, bb.w);

    float s  = (v0 + v1) + (v2 + v3);
    float s2 = fmaf(v0, v0, fmaf(v1, v1, fmaf(v2, v2, v3 * v3)));
#pragma unroll
    for (int m = 1; m < 32; m <<= 1) {
        s  += __shfl_xor_sync(0xffffffffu, s,  m);
        s2 += __shfl_xor_sync(0xffffffffu, s2, m);
    }
    float mu  = s * (1.f / 128.f);
    float var = s2 * (1.f / 128.f) - mu * mu;
    float inv = rsqrtf(var + LN_EPS);

    float4 gg = reinterpret_cast<const float4*>(gamma)[lane];
    float4 be = reinterpret_cast<const float4*>(beta)[lane];
    float4 o;
    o.x = fmaxf((v0 - mu) * inv * gg.x + be.x, 0.f);
    o.y = fmaxf((v1 - mu) * inv * gg.y + be.y, 0.f);
    o.z = fmaxf((v2 - mu) * inv * gg.z + be.z, 0.f);
    o.w = fmaxf((v3 - mu) * inv * gg.w + be.w, 0.f);
    reinterpret_cast<float4*>(op + (size_t)w * DD)[lane] = o;
}

extern "C" void kernel_launch(void* const* d_in, const int* in_sizes, int n_in,
                              void* d_out, int out_size) {
    const float* features = (const float*)d_in[0];
    const int*   src      = (const int*)d_in[1];
    const int*   dst      = (const int*)d_in[2];
    const float* W1  = (const float*)d_in[3];
    const float* b1  = (const float*)d_in[4];
    const float* g1  = (const float*)d_in[5];
    const float* be1 = (const float*)d_in[6];
    const float* W2  = (const float*)d_in[7];
    const float* b2  = (const float*)d_in[8];
    const float* g2  = (const float*)d_in[9];
    const float* be2 = (const float*)d_in[10];
    float* out = (float*)d_out;

    int n = in_sizes[0] / DD;   // 50000
    int e = in_sizes[1];        // 800000

    int nBlocks    = (n + 255) / 256;
    int eBlocks    = (e + 255) / 256;
    int scanBlocks = (n + 1023) / 1024;
    int gathBlocks = (int)(((long long)n * 32 + 255) / 256);
    int gemmBlocks = (n + 63) / 64;

    // ---- CSR prep ----
    zero_counts<<<nBlocks, 256>>>(n);
    deg_count<<<eBlocks, 256>>>(src, dst, e);
    scan_blocks<<<scanBlocks, 1024>>>(n);
    finalize_off<<<nBlocks, 256>>>(n, e, scanBlocks);

    // ---- layer 1: GEMM1 (t = features@W1 * iso) runs alongside fill_csr ----
    fill_gemm1<<<gemmBlocks + eBlocks, 256>>>(src, dst, e, features, W1, n, gemmBlocks);
    gather_ln<<<gathBlocks, 256>>>(b1, g1, be1, nullptr, n);   // -> g_h1

    // ---- layer 2 ----
    gemm_t<<<gemmBlocks, 256>>>(nullptr, W2, n);               // t = h1@W2 * iso
    gather_ln<<<gathBlocks, 256>>>(b2, g2, be2, out, n);       // -> out
}